// round 10
// baseline (speedup 1.0000x reference)
#include <cuda_runtime.h>

// Rules_67619965108887: out[b,s,r] = (a_i*b_j)*c_k, r = i*25+j*5+k,
//   a_i=f(x[i]), b_j=f(x[5+j]), c_k=f(x[10+k]), f(v)=(v==0)?1:v.
// Association (a*b)*c matches jnp.prod ascending order -> bitwise equal.
//
// R10 (resubmit after infra failure): five designs plateaued at 7.1-7.6us
// with NO pipe >47% -> latency/serialization bound, not throughput bound.
// Keep R8's minimal compute (rule-per-thread, hoisted indices, broadcast LDS,
// coalesced STG.32) but SOFTWARE-PIPELINE the CTA: 32 positions = 4 tiles x 8,
// double-buffered. Per iteration: issue next tile's LDG (registers) ->
// compute current tile from smem -> zero-fix + STS prefetched tile -> ONE
// barrier. The LDG round-trip hides under compute; barriers never wait on
// memory. Buffer safety with one bar/iter: iter k reads buf[k&1], writes
// buf[(k+1)&1], last read in iter k-1, protected by iter k-1's end barrier.

constexpr int THREADS   = 128;
constexpr int P_PER_CTA = 32;
constexpr int P_TILE    = 8;
constexpr int N_TILES   = P_PER_CTA / P_TILE;      // 4
constexpr int TILE_VEC4 = P_TILE * 15 / 4;         // 30
constexpr int IN_VEC4   = P_PER_CTA * 15 / 4;      // 120

__global__ __launch_bounds__(THREADS, 12)
void rules_fired_kernel(const float4* __restrict__ x4,
                        float* __restrict__ out) {
    __shared__ float sx[2][P_TILE * 16];           // 2 x 512 B, [buf][pos][16]

    const int t = threadIdx.x;
    const size_t cta = blockIdx.x;
    const bool is_loader = (t < TILE_VEC4);
    const bool is_worker = (t < 125);

    // ---- loop-invariant loader scatter indices ----
    int p_e[4], f_e[4];
    if (is_loader) {
        #pragma unroll
        for (int e = 0; e < 4; e++) {
            const int li = t * 4 + e;              // 0..119 within a tile
            p_e[e] = li / 15;
            f_e[e] = li - p_e[e] * 15;
        }
    }
    // ---- loop-invariant rule offsets ----
    int oa = 0, ob = 0, oc = 0;
    if (is_worker) {
        const int i  = t / 25;
        const int jj = t - i * 25;
        const int j  = jj / 5;
        oa = i;
        ob = 5 + j;
        oc = 10 + (jj - j * 5);
    }

    const float4* src = x4 + cta * IN_VEC4;

    // ---- prologue: stage tile 0 ----
    if (is_loader) {
        float4 v = src[t];
        float vals[4] = {v.x, v.y, v.z, v.w};
        #pragma unroll
        for (int e = 0; e < 4; e++)
            sx[0][p_e[e] * 16 + f_e[e]] = (vals[e] == 0.0f) ? 1.0f : vals[e];
    }
    __syncthreads();

    // ---- pipelined main loop ----
    #pragma unroll
    for (int k = 0; k < N_TILES; k++) {
        // 1) prefetch next tile into registers (latency overlaps compute)
        float4 v;
        const bool have = (k + 1 < N_TILES) && is_loader;
        if (have) v = src[(k + 1) * TILE_VEC4 + t];

        // 2) compute tile k: thread owns rule r = t for all 8 positions
        if (is_worker) {
            const float* s = sx[k & 1];
            float* o = out + ((size_t)cta * P_PER_CTA + k * P_TILE) * 125 + t;
            #pragma unroll
            for (int pp = 0; pp < P_TILE; pp++)
                o[pp * 125] =
                    (s[pp * 16 + oa] * s[pp * 16 + ob]) * s[pp * 16 + oc];
        }

        // 3) zero-fix + stage the prefetched tile into the other buffer
        if (have) {
            float vals[4] = {v.x, v.y, v.z, v.w};
            #pragma unroll
            for (int e = 0; e < 4; e++)
                sx[(k + 1) & 1][p_e[e] * 16 + f_e[e]] =
                    (vals[e] == 0.0f) ? 1.0f : vals[e];
        }
        __syncthreads();
    }
}

extern "C" void kernel_launch(void* const* d_in, const int* in_sizes, int n_in,
                              void* d_out, int out_size) {
    const float4* x4 = (const float4*)d_in[0];   // (B,S,15) float32, B*S=32768
    // d_in[1] = active_rules (compile-time structure), d_in[2] = epoch
    float* out = (float*)d_out;                  // (B,S,125) float32

    const int total_pos = in_sizes[0] / 15;      // 32768
    const int n_ctas = total_pos / P_PER_CTA;    // 1024

    rules_fired_kernel<<<n_ctas, THREADS>>>(x4, out);
}

// round 12
// speedup vs baseline: 1.2399x; 1.2399x over previous
#include <cuda_runtime.h>

// Rules_67619965108887: out[b,s,r] = (a_i*b_j)*c_k, r = i*25+j*5+k,
//   a_i=f(x[i]), b_j=f(x[5+j]), c_k=f(x[10+k]), f(v)=(v==0)?1:v.
// Association (a*b)*c matches jnp.prod ascending order -> bitwise equal.
//
// R11: barrier/staging experiments all regressed; flat designs pin at ~7.1us
// with no pipe >47%. This kernel removes smem AND barriers entirely:
// warp-autonomous, shuffle-based.
//   Per position (one warp): lanes 0-14 LDG the 15 floats (2 sectors,
//   coalesced) + zero-fix; lanes 0-24 build ab = shfl(v,i)*shfl(v,5+j);
//   4 rounds: r = lane+32*rd -> shfl(ab, r/5) * shfl(v, 10+r%5), coalesced
//   STG.32 (32 consecutive floats per round).
// All shuffle sources are loop-invariant. ~21 warp-instrs/position, zero
// sync, zero smem -> warps fully independent, latency self-hiding.

constexpr int THREADS    = 128;
constexpr int WARPS      = THREADS / 32;
constexpr int P_PER_WARP = 8;
constexpr int P_PER_CTA  = WARPS * P_PER_WARP;   // 32
constexpr unsigned FULL  = 0xFFFFFFFFu;

__global__ __launch_bounds__(THREADS)
void rules_fired_kernel(const float* __restrict__ x,
                        float* __restrict__ out) {
    const int t    = threadIdx.x;
    const int warp = t >> 5;
    const int lane = t & 31;

    // ---- loop-invariant shuffle sources ----
    // ab builder (meaningful for lane < 25): ij = lane = i*5 + j
    const int i_src = lane / 5;                 // a source lane
    const int b_src = 5 + (lane - 5 * i_src);   // b source lane
    // per-round consumers: r = lane + 32*rd; ij = r/5 (lane holding ab), k = r%5
    int ab_src[4], c_src[4];
    #pragma unroll
    for (int rd = 0; rd < 4; rd++) {
        const int r  = lane + 32 * rd;
        const int ij = r / 5;
        ab_src[rd] = ij;                        // 25 for r>=125: harmless, not stored
        c_src[rd]  = 10 + (r - 5 * ij);
    }

    const size_t p0 = ((size_t)blockIdx.x * WARPS + warp) * P_PER_WARP;

    #pragma unroll
    for (int pp = 0; pp < P_PER_WARP; pp++) {
        const size_t p = p0 + pp;

        // one coalesced 60-byte load per position; zero->one fix
        float v = 1.0f;
        if (lane < 15) {
            const float w = x[p * 15 + lane];
            v = (w == 0.0f) ? 1.0f : w;
        }

        // lanes 0..24 build their pairwise product ab[ij] = a_i * b_j
        const float a  = __shfl_sync(FULL, v, i_src);
        const float b  = __shfl_sync(FULL, v, b_src);
        const float ab = a * b;

        float* o = out + p * 125;
        #pragma unroll
        for (int rd = 0; rd < 4; rd++) {
            const float abr = __shfl_sync(FULL, ab, ab_src[rd]);
            const float c   = __shfl_sync(FULL, v,  c_src[rd]);
            const float res = abr * c;          // (a*b)*c: exact order
            const int r = lane + 32 * rd;
            if (rd < 3 || r < 125) o[r] = res;  // only last round predicated
        }
    }
}

extern "C" void kernel_launch(void* const* d_in, const int* in_sizes, int n_in,
                              void* d_out, int out_size) {
    const float* x = (const float*)d_in[0];     // (B,S,15) float32, B*S=32768
    // d_in[1] = active_rules (compile-time structure), d_in[2] = epoch
    float* out = (float*)d_out;                 // (B,S,125) float32

    const int total_pos = in_sizes[0] / 15;     // 32768
    const int n_ctas = total_pos / P_PER_CTA;   // 1024

    rules_fired_kernel<<<n_ctas, THREADS>>>(x, out);
}

// round 13
// speedup vs baseline: 1.2444x; 1.0037x over previous
#include <cuda_runtime.h>

// Rules_67619965108887: out[b,s,r] = (a_i*b_j)*c_k, r = i*25+j*5+k,
//   a_i=f(x[i]), b_j=f(x[5+j]), c_k=f(x[10+k]), f(v)=(v==0)?1:v.
// Association (a*b)*c matches jnp.prod ascending order -> bitwise equal.
//
// R13: R12 (warp-autonomous shuffle, no smem, no barriers) hit 6.59us but
// occ=31.6 / issue=27.5 -> latency-hiding deficit, all throughput floors are
// ~1-2us. Fix: 4x the resident warps and batch the loads.
//   - P_PER_WARP 8 -> 4, grid 1024 -> 2048 (13.8 CTAs/SM of ~12-16 cap).
//   - All 4 positions' LDGs issued BEFORE any shuffle chain (MLP=4/warp).
// Instruction count unchanged; exposed latency shrinks on both axes.

constexpr int THREADS    = 128;
constexpr int WARPS      = THREADS / 32;
constexpr int P_PER_WARP = 4;
constexpr int P_PER_CTA  = WARPS * P_PER_WARP;   // 16
constexpr unsigned FULL  = 0xFFFFFFFFu;

__global__ __launch_bounds__(THREADS)
void rules_fired_kernel(const float* __restrict__ x,
                        float* __restrict__ out) {
    const int t    = threadIdx.x;
    const int warp = t >> 5;
    const int lane = t & 31;

    // ---- loop-invariant shuffle sources ----
    // ab builder (meaningful for lane < 25): ij = lane = i*5 + j
    const int i_src = lane / 5;                 // a source lane
    const int b_src = 5 + (lane - 5 * i_src);   // b source lane
    // per-round consumers: r = lane + 32*rd; ij = r/5 (lane holding ab), k = r%5
    int ab_src[4], c_src[4];
    #pragma unroll
    for (int rd = 0; rd < 4; rd++) {
        const int r  = lane + 32 * rd;
        const int ij = r / 5;
        ab_src[rd] = ij;                        // 25 for r>=125: harmless, not stored
        c_src[rd]  = 10 + (r - 5 * ij);
    }

    const size_t p0 = ((size_t)blockIdx.x * WARPS + warp) * P_PER_WARP;

    // ---- batched loads: all 4 positions in flight before any chain ----
    float v[P_PER_WARP];
    #pragma unroll
    for (int pp = 0; pp < P_PER_WARP; pp++) {
        float w = 0.0f;
        if (lane < 15) w = x[(p0 + pp) * 15 + lane];   // 60B coalesced
        v[pp] = (w == 0.0f) ? 1.0f : w;                // lanes>=15 -> 1.0
    }

    // ---- shuffle chains + coalesced stores ----
    #pragma unroll
    for (int pp = 0; pp < P_PER_WARP; pp++) {
        const float a  = __shfl_sync(FULL, v[pp], i_src);
        const float b  = __shfl_sync(FULL, v[pp], b_src);
        const float ab = a * b;                 // lanes 0..24 hold ab[ij]

        float* o = out + (p0 + pp) * 125;
        #pragma unroll
        for (int rd = 0; rd < 4; rd++) {
            const float abr = __shfl_sync(FULL, ab,    ab_src[rd]);
            const float c   = __shfl_sync(FULL, v[pp], c_src[rd]);
            const float res = abr * c;          // (a*b)*c: exact order
            const int r = lane + 32 * rd;
            if (rd < 3 || r < 125) o[r] = res;  // only last round predicated
        }
    }
}

extern "C" void kernel_launch(void* const* d_in, const int* in_sizes, int n_in,
                              void* d_out, int out_size) {
    const float* x = (const float*)d_in[0];     // (B,S,15) float32, B*S=32768
    // d_in[1] = active_rules (compile-time structure), d_in[2] = epoch
    float* out = (float*)d_out;                 // (B,S,125) float32

    const int total_pos = in_sizes[0] / 15;     // 32768
    const int n_ctas = total_pos / P_PER_CTA;   // 2048

    rules_fired_kernel<<<n_ctas, THREADS>>>(x, out);
}